// round 9
// baseline (speedup 1.0000x reference)
#include <cuda_runtime.h>
#include <math.h>

#define BB   8
#define LL   2048
#define DD   128
#define HH   4
#define DKK  32

typedef unsigned long long ull;

// ---- packed fp32x2 helpers (sm_100a) --------------------------------------
__device__ __forceinline__ void fma2(ull &d, ull a, ull b) {
    asm("fma.rn.f32x2 %0, %1, %2, %0;" : "+l"(d) : "l"(a), "l"(b));
}
__device__ __forceinline__ ull mul2(ull a, ull b) {
    ull r; asm("mul.rn.f32x2 %0, %1, %2;" : "=l"(r) : "l"(a), "l"(b)); return r;
}
__device__ __forceinline__ ull pack2(float a, float b) {
    ull r; asm("mov.b64 %0, {%1, %2};" : "=l"(r) : "f"(a), "f"(b)); return r;
}
__device__ __forceinline__ float2 unpack2(ull v) {
    float2 f; asm("mov.b64 {%0, %1}, %2;" : "=f"(f.x), "=f"(f.y) : "l"(v)); return f;
}
__device__ __forceinline__ float ex2(float x) {
    float r; asm("ex2.approx.f32 %0, %1;" : "=f"(r) : "f"(x)); return r;
}

// Scratch (allocation-free: static device globals)
__device__ float g_q[BB*HH*LL*DKK];     // [b][h][l][dk]
__device__ float g_k[BB*HH*LL*DKK];
__device__ float g_v[BB*HH*LL*DKK];
__device__ float g_head[BB*LL*DD];      // [b][l][h*32+dk]

// ---------------------------------------------------------------------------
// Kernel 1: QKV projection.  q[b,h,l,k] = sum_d x[b,d,l] * W[h,d,k]
// grid = (L/256, B, 12). Block covers 256 l. Warp -> (l-half, 8-k slice).
// (Round-7 version, measured 68.6us — kept.)
// ---------------------------------------------------------------------------
__global__ void __launch_bounds__(256)
qkv_kernel(const float* __restrict__ x, const float* __restrict__ Wq,
           const float* __restrict__ Wk, const float* __restrict__ Wv) {
    int b  = blockIdx.y;
    int l0 = blockIdx.x * 256;
    int z  = blockIdx.z;
    int m  = z >> 2;
    int h  = z & 3;

    __shared__ __align__(16) ull ws2[DD * DKK];   // dup-packed weights, 32KB
    int tid = threadIdx.x;

    const float* W = (m == 0 ? Wq : (m == 1 ? Wk : Wv)) + h * DD * DKK;
    for (int i = tid; i < DD * DKK / 4; i += 256) {
        float4 w4 = ((const float4*)W)[i];
        ws2[i*4 + 0] = pack2(w4.x, w4.x);
        ws2[i*4 + 1] = pack2(w4.y, w4.y);
        ws2[i*4 + 2] = pack2(w4.z, w4.z);
        ws2[i*4 + 3] = pack2(w4.w, w4.w);
    }
    __syncthreads();

    int w    = tid >> 5, lane = tid & 31;
    int kq   = (w & 3) * 8;                 // 8-k slice per warp
    int lb   = (w >> 2) * 128 + lane * 4;   // l-half + lane*4 : coalesced LDG

    const float* xb = x + (size_t)b * DD * LL + l0 + lb;

    ull acc[2][8] = {};        // [l-pair][k], packed along l
    #pragma unroll 4
    for (int d = 0; d < DD; d++) {
        ulonglong2 x2 = *(const ulonglong2*)(xb + (size_t)d * LL);
        ulonglong2 wa = *(ulonglong2*)&ws2[d * DKK + kq];
        ulonglong2 wb = *(ulonglong2*)&ws2[d * DKK + kq + 2];
        ulonglong2 wc = *(ulonglong2*)&ws2[d * DKK + kq + 4];
        ulonglong2 wd = *(ulonglong2*)&ws2[d * DKK + kq + 6];
        fma2(acc[0][0], x2.x, wa.x); fma2(acc[1][0], x2.y, wa.x);
        fma2(acc[0][1], x2.x, wa.y); fma2(acc[1][1], x2.y, wa.y);
        fma2(acc[0][2], x2.x, wb.x); fma2(acc[1][2], x2.y, wb.x);
        fma2(acc[0][3], x2.x, wb.y); fma2(acc[1][3], x2.y, wb.y);
        fma2(acc[0][4], x2.x, wc.x); fma2(acc[1][4], x2.y, wc.x);
        fma2(acc[0][5], x2.x, wc.y); fma2(acc[1][5], x2.y, wc.y);
        fma2(acc[0][6], x2.x, wd.x); fma2(acc[1][6], x2.y, wd.x);
        fma2(acc[0][7], x2.x, wd.y); fma2(acc[1][7], x2.y, wd.y);
    }

    float* Gout = (m == 0 ? g_q : (m == 1 ? g_k : g_v));
    float* gp = Gout + ((size_t)(b * HH + h) * LL + l0) * DKK;
    #pragma unroll
    for (int ip = 0; ip < 2; ip++) {
        float2 f0 = unpack2(acc[ip][0]), f1 = unpack2(acc[ip][1]);
        float2 f2 = unpack2(acc[ip][2]), f3 = unpack2(acc[ip][3]);
        float2 f4 = unpack2(acc[ip][4]), f5 = unpack2(acc[ip][5]);
        float2 f6 = unpack2(acc[ip][6]), f7 = unpack2(acc[ip][7]);
        float* r0 = &gp[(lb + 2*ip) * DKK + kq];
        float* r1 = r0 + DKK;
        *(float4*)&r0[0] = make_float4(f0.x, f1.x, f2.x, f3.x);
        *(float4*)&r0[4] = make_float4(f4.x, f5.x, f6.x, f7.x);
        *(float4*)&r1[0] = make_float4(f0.y, f1.y, f2.y, f3.y);
        *(float4*)&r1[4] = make_float4(f4.y, f5.y, f6.y, f7.y);
    }
}

// ---------------------------------------------------------------------------
// Kernel 2: attention. 2 query rows per thread (t, t+128). Mask-compacted
// K/V tiles with DIRECT keeper-thread copy (round-4 form, fastest measured).
// q pre-scaled by log2e/sqrt(dk) so exp is a bare ex2.approx.
// __launch_bounds__(128,3): cap regs ~170 -> 3 blocks/SM (12 warps).
// ---------------------------------------------------------------------------
#define BN 128
__global__ void __launch_bounds__(128, 3)
attn_kernel(const float* __restrict__ mask) {
    __shared__ __align__(16) float ks[BN * DKK];
    __shared__ __align__(16) float vs[BN * DKK];
    __shared__ int wcnt[4];

    int b = blockIdx.z, h = blockIdx.y;
    int q0 = blockIdx.x * 256;
    int t  = threadIdx.x;
    int lane = t & 31, w = t >> 5;

    const float* qb = g_q + (size_t)(b * HH + h) * LL * DKK;
    const float* kp = g_k + (size_t)(b * HH + h) * LL * DKK;
    const float* vp = g_v + (size_t)(b * HH + h) * LL * DKK;

    const float scale = 0.17677669529663687f * 1.4426950408889634f; // log2e/sqrt(32)
    ull sc2 = pack2(scale, scale);

    ull qA[16], qB[16];
    {
        const ulonglong2* pA = (const ulonglong2*)(qb + (size_t)(q0 + t) * DKK);
        const ulonglong2* pB = (const ulonglong2*)(qb + (size_t)(q0 + t + 128) * DKK);
        #pragma unroll
        for (int p = 0; p < 8; p++) {
            ulonglong2 a = pA[p], c = pB[p];
            qA[2*p] = mul2(a.x, sc2); qA[2*p+1] = mul2(a.y, sc2);
            qB[2*p] = mul2(c.x, sc2); qB[2*p+1] = mul2(c.y, sc2);
        }
    }
    float maskA = mask[b * LL + q0 + t];
    float maskB = mask[b * LL + q0 + t + 128];

    ull oA[16], oB[16];
    #pragma unroll
    for (int p = 0; p < 16; p++) { oA[p] = 0ULL; oB[p] = 0ULL; }
    float lsumA = 0.f, lsumB = 0.f;

    for (int kt = 0; kt < LL; kt += BN) {
        __syncthreads();   // previous tile fully consumed
        // --- mask-compacting tile load: thread t owns key kt+t ---
        float kmv = mask[b * LL + kt + t];
        int keep = (kmv <= 0.5f);
        unsigned bal = __ballot_sync(0xffffffffu, keep);
        if (lane == 0) wcnt[w] = __popc(bal);
        __syncthreads();
        int c0 = wcnt[0], c1 = wcnt[1], c2 = wcnt[2], c3 = wcnt[3];
        int nk = c0 + c1 + c2 + c3;
        if (keep) {
            int base = (w > 0 ? c0 : 0) + (w > 1 ? c1 : 0) + (w > 2 ? c2 : 0);
            int pos = base + __popc(bal & ((1u << lane) - 1u));
            const float4* krow = (const float4*)(kp + (size_t)(kt + t) * DKK);
            const float4* vrow = (const float4*)(vp + (size_t)(kt + t) * DKK);
            float4* kd = (float4*)&ks[pos * DKK];
            float4* vd = (float4*)&vs[pos * DKK];
            #pragma unroll
            for (int p = 0; p < 8; p++) { kd[p] = krow[p]; vd[p] = vrow[p]; }
        }
        __syncthreads();

        // --- branch-free inner loop over kept keys ---
        #pragma unroll 2
        for (int j = 0; j < nk; j++) {
            const ulonglong2* kj = (const ulonglong2*)&ks[j * DKK];
            ull a0 = 0, a1 = 0, b0 = 0, b1 = 0;
            #pragma unroll
            for (int p = 0; p < 8; p++) {
                ulonglong2 kk = kj[p];
                fma2(a0, qA[2*p],   kk.x);
                fma2(a1, qA[2*p+1], kk.y);
                fma2(b0, qB[2*p],   kk.x);
                fma2(b1, qB[2*p+1], kk.y);
            }
            float2 fa0 = unpack2(a0), fa1 = unpack2(a1);
            float2 fb0 = unpack2(b0), fb1 = unpack2(b1);
            float pA = ex2((fa0.x + fa0.y) + (fa1.x + fa1.y));
            float pB = ex2((fb0.x + fb0.y) + (fb1.x + fb1.y));
            lsumA += pA; lsumB += pB;
            ull pA2 = pack2(pA, pA), pB2 = pack2(pB, pB);
            const ulonglong2* vj = (const ulonglong2*)&vs[j * DKK];
            #pragma unroll
            for (int p = 0; p < 8; p++) {
                ulonglong2 vv = vj[p];
                fma2(oA[2*p],   pA2, vv.x);
                fma2(oA[2*p+1], pA2, vv.y);
                fma2(oB[2*p],   pB2, vv.x);
                fma2(oB[2*p+1], pB2, vv.y);
            }
        }
    }

    float invA = maskA / lsumA;
    float invB = maskB / lsumB;
    float* hpA = g_head + ((size_t)b * LL + q0 + t) * DD + h * DKK;
    float* hpB = g_head + ((size_t)b * LL + q0 + t + 128) * DD + h * DKK;
    #pragma unroll
    for (int p = 0; p < 8; p++) {
        float2 a0 = unpack2(oA[2*p]), a1 = unpack2(oA[2*p+1]);
        float2 b0 = unpack2(oB[2*p]), b1 = unpack2(oB[2*p+1]);
        *(float4*)&hpA[p*4] = make_float4(a0.x*invA, a0.y*invA, a1.x*invA, a1.y*invA);
        *(float4*)&hpB[p*4] = make_float4(b0.x*invB, b0.y*invB, b1.x*invB, b1.y*invB);
    }
}

// ---------------------------------------------------------------------------
// Kernel 3: output projection + transpose.
// out[b,m,l] = sum_c head[b,l,c] * Wo[c,m]. grid z splits m into 2 halves.
// ---------------------------------------------------------------------------
#define OPAD 134
__global__ void __launch_bounds__(256)
out_kernel(const float* __restrict__ Wo, float* __restrict__ out) {
    int b  = blockIdx.y;
    int l0 = blockIdx.x * 128;
    int mz = blockIdx.z;              // m half: 0 or 1
    extern __shared__ __align__(16) float sm[];
    float* hst = sm;                  // [c=128][OPAD]  hst[c][l]
    float* wos = sm + 128 * OPAD;     // [c=128][64]  this m-half of Wo
    int tid = threadIdx.x;

    const float* hb = g_head + ((size_t)b * LL + l0) * DD;
    for (int i = tid; i < 128 * 32; i += 256) {
        int l = i >> 5, c4 = (i & 31) * 4;
        float4 v = *(const float4*)&hb[l * DD + c4];
        hst[(c4 + 0) * OPAD + l] = v.x;
        hst[(c4 + 1) * OPAD + l] = v.y;
        hst[(c4 + 2) * OPAD + l] = v.z;
        hst[(c4 + 3) * OPAD + l] = v.w;
    }
    for (int i = tid; i < 128 * 16; i += 256) {
        int c = i >> 4, m4 = (i & 15) * 4;
        *(float4*)&wos[c * 64 + m4] = *(const float4*)&Wo[c * DD + mz * 64 + m4];
    }
    __syncthreads();

    int mb  = (tid >> 4) * 4;         // 16 m-groups * 4 (within half)
    int lb2 = (tid & 15) * 8;         // 16 l-groups * 8

    ull acc[4][4] = {};               // [m][l-pair]
    #pragma unroll 4
    for (int c = 0; c < 128; c++) {
        const ull* hp = (const ull*)&hst[c * OPAD + lb2];   // even index -> 8B aligned
        ull h0 = hp[0], h1 = hp[1], h2 = hp[2], h3 = hp[3];
        float4 w4 = *(float4*)&wos[c * 64 + mb];
        ull w0 = pack2(w4.x, w4.x), w1 = pack2(w4.y, w4.y);
        ull w2 = pack2(w4.z, w4.z), w3 = pack2(w4.w, w4.w);
        fma2(acc[0][0], w0, h0); fma2(acc[0][1], w0, h1); fma2(acc[0][2], w0, h2); fma2(acc[0][3], w0, h3);
        fma2(acc[1][0], w1, h0); fma2(acc[1][1], w1, h1); fma2(acc[1][2], w1, h2); fma2(acc[1][3], w1, h3);
        fma2(acc[2][0], w2, h0); fma2(acc[2][1], w2, h1); fma2(acc[2][2], w2, h2); fma2(acc[2][3], w2, h3);
        fma2(acc[3][0], w3, h0); fma2(acc[3][1], w3, h1); fma2(acc[3][2], w3, h2); fma2(acc[3][3], w3, h3);
    }
    #pragma unroll
    for (int i = 0; i < 4; i++) {
        float2 f0 = unpack2(acc[i][0]), f1 = unpack2(acc[i][1]);
        float2 f2 = unpack2(acc[i][2]), f3 = unpack2(acc[i][3]);
        float* op = out + ((size_t)b * DD + mz * 64 + mb + i) * LL + l0 + lb2;
        *(float4*)&op[0] = make_float4(f0.x, f0.y, f1.x, f1.y);
        *(float4*)&op[4] = make_float4(f2.x, f2.y, f3.x, f3.y);
    }
}

// ---------------------------------------------------------------------------
extern "C" void kernel_launch(void* const* d_in, const int* in_sizes, int n_in,
                              void* d_out, int out_size) {
    const float* x    = (const float*)d_in[0];
    const float* mask = (const float*)d_in[1];
    const float* Wq   = (const float*)d_in[2];
    const float* Wk   = (const float*)d_in[3];
    const float* Wv   = (const float*)d_in[4];
    const float* Wo   = (const float*)d_in[5];
    float* out = (float*)d_out;

    const int OUT_SMEM = (128 * OPAD + 128 * 64) * 4;          // ~100.6 KB
    cudaFuncSetAttribute(out_kernel, cudaFuncAttributeMaxDynamicSharedMemorySize, OUT_SMEM);

    qkv_kernel<<<dim3(LL / 256, BB, 12), 256>>>(x, Wq, Wk, Wv);
    attn_kernel<<<dim3(LL / 256, HH, BB), 128>>>(mask);
    out_kernel<<<dim3(LL / 128, BB, 2), 256, OUT_SMEM>>>(Wo, out);
}

// round 10
// speedup vs baseline: 1.0038x; 1.0038x over previous
#include <cuda_runtime.h>
#include <math.h>

#define BB   8
#define LL   2048
#define DD   128
#define HH   4
#define DKK  32

typedef unsigned long long ull;

// ---- packed fp32x2 helpers (sm_100a) --------------------------------------
__device__ __forceinline__ void fma2(ull &d, ull a, ull b) {
    asm("fma.rn.f32x2 %0, %1, %2, %0;" : "+l"(d) : "l"(a), "l"(b));
}
__device__ __forceinline__ ull mul2(ull a, ull b) {
    ull r; asm("mul.rn.f32x2 %0, %1, %2;" : "=l"(r) : "l"(a), "l"(b)); return r;
}
__device__ __forceinline__ ull pack2(float a, float b) {
    ull r; asm("mov.b64 %0, {%1, %2};" : "=l"(r) : "f"(a), "f"(b)); return r;
}
__device__ __forceinline__ float2 unpack2(ull v) {
    float2 f; asm("mov.b64 {%0, %1}, %2;" : "=f"(f.x), "=f"(f.y) : "l"(v)); return f;
}
__device__ __forceinline__ float ex2(float x) {
    float r; asm("ex2.approx.f32 %0, %1;" : "=f"(r) : "f"(x)); return r;
}

// Scratch (allocation-free: static device globals)
__device__ float g_q[BB*HH*LL*DKK];     // [b][h][l][dk]
__device__ float g_k[BB*HH*LL*DKK];
__device__ float g_v[BB*HH*LL*DKK];
__device__ float g_head[BB*LL*DD];      // [b][l][h*32+dk]

// ---------------------------------------------------------------------------
// Kernel 1: QKV projection.  q[b,h,l,k] = sum_d x[b,d,l] * W[h,d,k]
// grid = (L/256, B, 12). Block covers 256 l. Warp -> (l-half, 8-k slice).
// (Round-7 version, measured 68.6us — kept.)
// ---------------------------------------------------------------------------
__global__ void __launch_bounds__(256)
qkv_kernel(const float* __restrict__ x, const float* __restrict__ Wq,
           const float* __restrict__ Wk, const float* __restrict__ Wv) {
    int b  = blockIdx.y;
    int l0 = blockIdx.x * 256;
    int z  = blockIdx.z;
    int m  = z >> 2;
    int h  = z & 3;

    __shared__ __align__(16) ull ws2[DD * DKK];   // dup-packed weights, 32KB
    int tid = threadIdx.x;

    const float* W = (m == 0 ? Wq : (m == 1 ? Wk : Wv)) + h * DD * DKK;
    for (int i = tid; i < DD * DKK / 4; i += 256) {
        float4 w4 = ((const float4*)W)[i];
        ws2[i*4 + 0] = pack2(w4.x, w4.x);
        ws2[i*4 + 1] = pack2(w4.y, w4.y);
        ws2[i*4 + 2] = pack2(w4.z, w4.z);
        ws2[i*4 + 3] = pack2(w4.w, w4.w);
    }
    __syncthreads();

    int w    = tid >> 5, lane = tid & 31;
    int kq   = (w & 3) * 8;                 // 8-k slice per warp
    int lb   = (w >> 2) * 128 + lane * 4;   // l-half + lane*4 : coalesced LDG

    const float* xb = x + (size_t)b * DD * LL + l0 + lb;

    ull acc[2][8] = {};        // [l-pair][k], packed along l
    #pragma unroll 4
    for (int d = 0; d < DD; d++) {
        ulonglong2 x2 = *(const ulonglong2*)(xb + (size_t)d * LL);
        ulonglong2 wa = *(ulonglong2*)&ws2[d * DKK + kq];
        ulonglong2 wb = *(ulonglong2*)&ws2[d * DKK + kq + 2];
        ulonglong2 wc = *(ulonglong2*)&ws2[d * DKK + kq + 4];
        ulonglong2 wd = *(ulonglong2*)&ws2[d * DKK + kq + 6];
        fma2(acc[0][0], x2.x, wa.x); fma2(acc[1][0], x2.y, wa.x);
        fma2(acc[0][1], x2.x, wa.y); fma2(acc[1][1], x2.y, wa.y);
        fma2(acc[0][2], x2.x, wb.x); fma2(acc[1][2], x2.y, wb.x);
        fma2(acc[0][3], x2.x, wb.y); fma2(acc[1][3], x2.y, wb.y);
        fma2(acc[0][4], x2.x, wc.x); fma2(acc[1][4], x2.y, wc.x);
        fma2(acc[0][5], x2.x, wc.y); fma2(acc[1][5], x2.y, wc.y);
        fma2(acc[0][6], x2.x, wd.x); fma2(acc[1][6], x2.y, wd.x);
        fma2(acc[0][7], x2.x, wd.y); fma2(acc[1][7], x2.y, wd.y);
    }

    float* Gout = (m == 0 ? g_q : (m == 1 ? g_k : g_v));
    float* gp = Gout + ((size_t)(b * HH + h) * LL + l0) * DKK;
    #pragma unroll
    for (int ip = 0; ip < 2; ip++) {
        float2 f0 = unpack2(acc[ip][0]), f1 = unpack2(acc[ip][1]);
        float2 f2 = unpack2(acc[ip][2]), f3 = unpack2(acc[ip][3]);
        float2 f4 = unpack2(acc[ip][4]), f5 = unpack2(acc[ip][5]);
        float2 f6 = unpack2(acc[ip][6]), f7 = unpack2(acc[ip][7]);
        float* r0 = &gp[(lb + 2*ip) * DKK + kq];
        float* r1 = r0 + DKK;
        *(float4*)&r0[0] = make_float4(f0.x, f1.x, f2.x, f3.x);
        *(float4*)&r0[4] = make_float4(f4.x, f5.x, f6.x, f7.x);
        *(float4*)&r1[0] = make_float4(f0.y, f1.y, f2.y, f3.y);
        *(float4*)&r1[4] = make_float4(f4.y, f5.y, f6.y, f7.y);
    }
}

// ---------------------------------------------------------------------------
// Kernel 2: attention. 2 query rows per thread (t, t+128). Mask-compacted
// K/V tiles with DIRECT keeper-thread copy (round-4 form, fastest measured).
// q pre-scaled by log2e/sqrt(dk) so exp is a bare ex2.approx.
// __launch_bounds__(128,3): cap regs ~170 -> 3 blocks/SM (12 warps).
// ---------------------------------------------------------------------------
#define BN 128
__global__ void __launch_bounds__(128, 3)
attn_kernel(const float* __restrict__ mask) {
    __shared__ __align__(16) float ks[BN * DKK];
    __shared__ __align__(16) float vs[BN * DKK];
    __shared__ int wcnt[4];

    int b = blockIdx.z, h = blockIdx.y;
    int q0 = blockIdx.x * 256;
    int t  = threadIdx.x;
    int lane = t & 31, w = t >> 5;

    const float* qb = g_q + (size_t)(b * HH + h) * LL * DKK;
    const float* kp = g_k + (size_t)(b * HH + h) * LL * DKK;
    const float* vp = g_v + (size_t)(b * HH + h) * LL * DKK;

    const float scale = 0.17677669529663687f * 1.4426950408889634f; // log2e/sqrt(32)
    ull sc2 = pack2(scale, scale);

    ull qA[16], qB[16];
    {
        const ulonglong2* pA = (const ulonglong2*)(qb + (size_t)(q0 + t) * DKK);
        const ulonglong2* pB = (const ulonglong2*)(qb + (size_t)(q0 + t + 128) * DKK);
        #pragma unroll
        for (int p = 0; p < 8; p++) {
            ulonglong2 a = pA[p], c = pB[p];
            qA[2*p] = mul2(a.x, sc2); qA[2*p+1] = mul2(a.y, sc2);
            qB[2*p] = mul2(c.x, sc2); qB[2*p+1] = mul2(c.y, sc2);
        }
    }
    float maskA = mask[b * LL + q0 + t];
    float maskB = mask[b * LL + q0 + t + 128];

    ull oA[16], oB[16];
    #pragma unroll
    for (int p = 0; p < 16; p++) { oA[p] = 0ULL; oB[p] = 0ULL; }
    float lsumA = 0.f, lsumB = 0.f;

    for (int kt = 0; kt < LL; kt += BN) {
        __syncthreads();   // previous tile fully consumed
        // --- mask-compacting tile load: thread t owns key kt+t ---
        float kmv = mask[b * LL + kt + t];
        int keep = (kmv <= 0.5f);
        unsigned bal = __ballot_sync(0xffffffffu, keep);
        if (lane == 0) wcnt[w] = __popc(bal);
        __syncthreads();
        int c0 = wcnt[0], c1 = wcnt[1], c2 = wcnt[2], c3 = wcnt[3];
        int nk = c0 + c1 + c2 + c3;
        if (keep) {
            int base = (w > 0 ? c0 : 0) + (w > 1 ? c1 : 0) + (w > 2 ? c2 : 0);
            int pos = base + __popc(bal & ((1u << lane) - 1u));
            const float4* krow = (const float4*)(kp + (size_t)(kt + t) * DKK);
            const float4* vrow = (const float4*)(vp + (size_t)(kt + t) * DKK);
            float4* kd = (float4*)&ks[pos * DKK];
            float4* vd = (float4*)&vs[pos * DKK];
            #pragma unroll
            for (int p = 0; p < 8; p++) { kd[p] = krow[p]; vd[p] = vrow[p]; }
        }
        __syncthreads();

        // --- branch-free inner loop over kept keys ---
        #pragma unroll 2
        for (int j = 0; j < nk; j++) {
            const ulonglong2* kj = (const ulonglong2*)&ks[j * DKK];
            ull a0 = 0, a1 = 0, b0 = 0, b1 = 0;
            #pragma unroll
            for (int p = 0; p < 8; p++) {
                ulonglong2 kk = kj[p];
                fma2(a0, qA[2*p],   kk.x);
                fma2(a1, qA[2*p+1], kk.y);
                fma2(b0, qB[2*p],   kk.x);
                fma2(b1, qB[2*p+1], kk.y);
            }
            float2 fa0 = unpack2(a0), fa1 = unpack2(a1);
            float2 fb0 = unpack2(b0), fb1 = unpack2(b1);
            float pA = ex2((fa0.x + fa0.y) + (fa1.x + fa1.y));
            float pB = ex2((fb0.x + fb0.y) + (fb1.x + fb1.y));
            lsumA += pA; lsumB += pB;
            ull pA2 = pack2(pA, pA), pB2 = pack2(pB, pB);
            const ulonglong2* vj = (const ulonglong2*)&vs[j * DKK];
            #pragma unroll
            for (int p = 0; p < 8; p++) {
                ulonglong2 vv = vj[p];
                fma2(oA[2*p],   pA2, vv.x);
                fma2(oA[2*p+1], pA2, vv.y);
                fma2(oB[2*p],   pB2, vv.x);
                fma2(oB[2*p+1], pB2, vv.y);
            }
        }
    }

    float invA = maskA / lsumA;
    float invB = maskB / lsumB;
    float* hpA = g_head + ((size_t)b * LL + q0 + t) * DD + h * DKK;
    float* hpB = g_head + ((size_t)b * LL + q0 + t + 128) * DD + h * DKK;
    #pragma unroll
    for (int p = 0; p < 8; p++) {
        float2 a0 = unpack2(oA[2*p]), a1 = unpack2(oA[2*p+1]);
        float2 b0 = unpack2(oB[2*p]), b1 = unpack2(oB[2*p+1]);
        *(float4*)&hpA[p*4] = make_float4(a0.x*invA, a0.y*invA, a1.x*invA, a1.y*invA);
        *(float4*)&hpB[p*4] = make_float4(b0.x*invB, b0.y*invB, b1.x*invB, b1.y*invB);
    }
}

// ---------------------------------------------------------------------------
// Kernel 3: output projection + transpose.
// out[b,m,l] = sum_c head[b,l,c] * Wo[c,m]. grid z splits m into 2 halves.
// ---------------------------------------------------------------------------
#define OPAD 134
__global__ void __launch_bounds__(256)
out_kernel(const float* __restrict__ Wo, float* __restrict__ out) {
    int b  = blockIdx.y;
    int l0 = blockIdx.x * 128;
    int mz = blockIdx.z;              // m half: 0 or 1
    extern __shared__ __align__(16) float sm[];
    float* hst = sm;                  // [c=128][OPAD]  hst[c][l]
    float* wos = sm + 128 * OPAD;     // [c=128][64]  this m-half of Wo
    int tid = threadIdx.x;

    const float* hb = g_head + ((size_t)b * LL + l0) * DD;
    for (int i = tid; i < 128 * 32; i += 256) {
        int l = i >> 5, c4 = (i & 31) * 4;
        float4 v = *(const float4*)&hb[l * DD + c4];
        hst[(c4 + 0) * OPAD + l] = v.x;
        hst[(c4 + 1) * OPAD + l] = v.y;
        hst[(c4 + 2) * OPAD + l] = v.z;
        hst[(c4 + 3) * OPAD + l] = v.w;
    }
    for (int i = tid; i < 128 * 16; i += 256) {
        int c = i >> 4, m4 = (i & 15) * 4;
        *(float4*)&wos[c * 64 + m4] = *(const float4*)&Wo[c * DD + mz * 64 + m4];
    }
    __syncthreads();

    int mb  = (tid >> 4) * 4;         // 16 m-groups * 4 (within half)
    int lb2 = (tid & 15) * 8;         // 16 l-groups * 8

    ull acc[4][4] = {};               // [m][l-pair]
    #pragma unroll 4
    for (int c = 0; c < 128; c++) {
        const ull* hp = (const ull*)&hst[c * OPAD + lb2];   // even index -> 8B aligned
        ull h0 = hp[0], h1 = hp[1], h2 = hp[2], h3 = hp[3];
        float4 w4 = *(float4*)&wos[c * 64 + mb];
        ull w0 = pack2(w4.x, w4.x), w1 = pack2(w4.y, w4.y);
        ull w2 = pack2(w4.z, w4.z), w3 = pack2(w4.w, w4.w);
        fma2(acc[0][0], w0, h0); fma2(acc[0][1], w0, h1); fma2(acc[0][2], w0, h2); fma2(acc[0][3], w0, h3);
        fma2(acc[1][0], w1, h0); fma2(acc[1][1], w1, h1); fma2(acc[1][2], w1, h2); fma2(acc[1][3], w1, h3);
        fma2(acc[2][0], w2, h0); fma2(acc[2][1], w2, h1); fma2(acc[2][2], w2, h2); fma2(acc[2][3], w2, h3);
        fma2(acc[3][0], w3, h0); fma2(acc[3][1], w3, h1); fma2(acc[3][2], w3, h2); fma2(acc[3][3], w3, h3);
    }
    #pragma unroll
    for (int i = 0; i < 4; i++) {
        float2 f0 = unpack2(acc[i][0]), f1 = unpack2(acc[i][1]);
        float2 f2 = unpack2(acc[i][2]), f3 = unpack2(acc[i][3]);
        float* op = out + ((size_t)b * DD + mz * 64 + mb + i) * LL + l0 + lb2;
        *(float4*)&op[0] = make_float4(f0.x, f0.y, f1.x, f1.y);
        *(float4*)&op[4] = make_float4(f2.x, f2.y, f3.x, f3.y);
    }
}

// ---------------------------------------------------------------------------
extern "C" void kernel_launch(void* const* d_in, const int* in_sizes, int n_in,
                              void* d_out, int out_size) {
    const float* x    = (const float*)d_in[0];
    const float* mask = (const float*)d_in[1];
    const float* Wq   = (const float*)d_in[2];
    const float* Wk   = (const float*)d_in[3];
    const float* Wv   = (const float*)d_in[4];
    const float* Wo   = (const float*)d_in[5];
    float* out = (float*)d_out;

    const int OUT_SMEM = (128 * OPAD + 128 * 64) * 4;          // ~100.6 KB
    cudaFuncSetAttribute(out_kernel, cudaFuncAttributeMaxDynamicSharedMemorySize, OUT_SMEM);

    qkv_kernel<<<dim3(LL / 256, BB, 12), 256>>>(x, Wq, Wk, Wv);
    attn_kernel<<<dim3(LL / 256, HH, BB), 128>>>(mask);
    out_kernel<<<dim3(LL / 128, BB, 2), 256, OUT_SMEM>>>(Wo, out);
}